// round 1
// baseline (speedup 1.0000x reference)
#include <cuda_runtime.h>

#define PP 2
#define BB 96
#define AA 32
#define NN (BB*AA)            // 3072 atoms per pose
#define MD 4
#define MA 4
#define NPOLB (MD+MA)         // 8 polars per residue block
#define NPOL (PP*BB*NPOLB)    // 1536 polar sites total
#define C_LK 0.0897935610625833f
#define SLICES 4
#define TPB 256

struct alignas(16) PolarData {
    float4 w0;   // water0 xyz, .w = ri
    float4 w1;   // water1 xyz, .w = scale = C_LK*dgi/lami
    float4 xp;   // polar atom xyz, .w = 1/lami
    int a_i; int valid; int pad0; int pad1;
};  // 64 bytes = 16 words

__device__ PolarData g_polar[NPOL];
__device__ float4    g_atom[PP*NN];   // xyz, .w = rj
__device__ float     g_vol[PP*NN];    // heavy ? volj : 0

// ---------------------------------------------------------------------------
// Setup kernel: per-atom staging + water generation + output zeroing
// ---------------------------------------------------------------------------
__global__ void lkball_setup_kernel(
    const float* __restrict__ coords,      // (P,N,3)
    const int*   __restrict__ block_type,  // (P,B)
    const int*   __restrict__ bonds,       // (NT,A,2)
    const int*   __restrict__ ranges,      // (NT,A,2)
    const int*   __restrict__ n_donH,      // (NT,)
    const int*   __restrict__ n_acc,       // (NT,)
    const int*   __restrict__ donH_inds,   // (NT,MD)
    const int*   __restrict__ don_hvy,     // (NT,MD)
    const int*   __restrict__ acc_inds,    // (NT,MA)
    const int*   __restrict__ hyb,         // (NT,MA)
    const int*   __restrict__ is_h,        // (NT,A)
    const float* __restrict__ params,      // (NT,A,4)
    const float* __restrict__ wgen,        // (2,) dist, angle
    const float* __restrict__ sp2t,
    const float* __restrict__ sp3t,
    const float* __restrict__ ringt,
    float* __restrict__ out)
{
    int t = blockIdx.x * blockDim.x + threadIdx.x;

    if (t < 2 * PP) out[t] = 0.0f;   // zero poisoned output (shape (2,P))

    // -------- per-atom staging --------
    if (t < PP * NN) {
        int p  = t / NN;
        int j  = t % NN;
        int bj = j >> 5;          // j / AA
        int aj = j & 31;          // j % AA
        int bt = block_type[p * BB + bj];
        const float* c = coords + 3 * t;
        float rj  = params[(bt * AA + aj) * 4 + 0];
        float vol = params[(bt * AA + aj) * 4 + 3];
        int   hy  = is_h[bt * AA + aj];
        g_atom[t] = make_float4(c[0], c[1], c[2], rj);
        g_vol[t]  = hy ? 0.0f : vol;
    }

    // -------- per-polar water generation --------
    if (t < NPOL) {
        int p = t / (BB * NPOLB);
        int r = t % (BB * NPOLB);
        int b = r / NPOLB;
        int k = r % NPOLB;
        int bt = block_type[p * BB + b];
        const float* cblk = coords + ((size_t)(p * BB + b) * AA) * 3;

        float wdist = wgen[0];
        float wang  = wgen[1];

        float w0x, w0y, w0z, w1x, w1y, w1z;
        int a_i, valid;

        if (k < MD) {
            // donor: water along heavy->H direction
            valid = (k < n_donH[bt]) ? 1 : 0;
            int hv = don_hvy[bt * MD + k];
            int hi = donH_inds[bt * MD + k];
            float hx = cblk[3*hv+0], hy_ = cblk[3*hv+1], hz = cblk[3*hv+2];
            float Hx = cblk[3*hi+0], Hy = cblk[3*hi+1], Hz = cblk[3*hi+2];
            float dx = Hx - hx, dy = Hy - hy_, dz = Hz - hz;
            float inv = rsqrtf(dx*dx + dy*dy + dz*dz + 1e-12f);
            float s = wdist * inv;
            w0x = hx + s*dx; w0y = hy_ + s*dy; w0z = hz + s*dz;
            // water 1 masked out -> far-away sentinel (d2 ~3e8 >> d2_low+ramp2)
            w1x = 1e4f; w1y = 1e4f; w1z = 1e4f;
            a_i = hv;
        } else {
            int k2 = k - MD;
            valid = (k2 < n_acc[bt]) ? 1 : 0;
            int acc = acc_inds[bt * MA + k2];
            int r0a   = ranges[(bt * AA + acc) * 2 + 0];
            int base  = bonds[(bt * AA + r0a) * 2 + 1];
            int r0b   = ranges[(bt * AA + base) * 2 + 0];
            int base2 = bonds[(bt * AA + r0b) * 2 + 1];
            float cx = cblk[3*acc+0],   cy = cblk[3*acc+1],   cz = cblk[3*acc+2];
            float bx = cblk[3*base+0],  by = cblk[3*base+1],  bz = cblk[3*base+2];
            float ax = cblk[3*base2+0], ay = cblk[3*base2+1], az = cblk[3*base2+2];
            // e1 = norm(c - b)
            float e1x = cx - bx, e1y = cy - by, e1z = cz - bz;
            float inv1 = rsqrtf(e1x*e1x + e1y*e1y + e1z*e1z + 1e-12f);
            e1x *= inv1; e1y *= inv1; e1z *= inv1;
            // nrm = norm(cross(b - a, e1))
            float ux = bx - ax, uy = by - ay, uz = bz - az;
            float nx = uy*e1z - uz*e1y;
            float ny = uz*e1x - ux*e1z;
            float nz = ux*e1y - uy*e1x;
            float inv2 = rsqrtf(nx*nx + ny*ny + nz*nz + 1e-12f);
            nx *= inv2; ny *= inv2; nz *= inv2;
            // e2 = cross(nrm, e1)
            float e2x = ny*e1z - nz*e1y;
            float e2y = nz*e1x - nx*e1z;
            float e2z = nx*e1y - ny*e1x;
            int h = hyb[bt * MA + k2];
            const float* tors = (h == 0) ? sp2t : ((h == 1) ? sp3t : ringt);
            float chi0 = tors[0], chi1 = tors[1];
            float ct = cosf(wang), st = sinf(wang);
            float f1 = -wdist * ct;           // coefficient on e1
            float fw = wdist * st;
            float c0 = fw * cosf(chi0), s0_ = fw * sinf(chi0);
            float c1 = fw * cosf(chi1), s1_ = fw * sinf(chi1);
            w0x = cx + f1*e1x + c0*e2x + s0_*nx;
            w0y = cy + f1*e1y + c0*e2y + s0_*ny;
            w0z = cz + f1*e1z + c0*e2z + s0_*nz;
            w1x = cx + f1*e1x + c1*e2x + s1_*nx;
            w1y = cy + f1*e1y + c1*e2y + s1_*ny;
            w1z = cz + f1*e1z + c1*e2z + s1_*nz;
            a_i = acc;
        }

        float ri   = params[(bt * AA + a_i) * 4 + 0];
        float dgi  = params[(bt * AA + a_i) * 4 + 1];
        float lami = params[(bt * AA + a_i) * 4 + 2];
        float inv_lami = 1.0f / lami;
        float scale = C_LK * dgi * inv_lami;

        PolarData pd;
        pd.w0 = make_float4(w0x, w0y, w0z, ri);
        pd.w1 = make_float4(w1x, w1y, w1z, scale);
        pd.xp = make_float4(cblk[3*a_i+0], cblk[3*a_i+1], cblk[3*a_i+2], inv_lami);
        pd.a_i = a_i; pd.valid = valid; pd.pad0 = 0; pd.pad1 = 0;
        g_polar[t] = pd;
    }
}

// ---------------------------------------------------------------------------
// Pair kernel: one block per (pose, residue-block, j-slice).
// All 8 polars of the residue block are processed together so each atom-j
// load is amortized 8x. Polar data lives in SMEM (broadcast reads).
// ---------------------------------------------------------------------------
__global__ __launch_bounds__(TPB)
void lkball_pair_kernel(
    const float* __restrict__ gparams,     // (3,) cutoff, ramp2, d2_low
    const int*   __restrict__ minsep,      // (P,B,B)
    const int*   __restrict__ pathdist,    // (NT,A,A)
    const int*   __restrict__ block_type,  // (P,B)
    float* __restrict__ out)               // (2,P)
{
    __shared__ PolarData sp[NPOLB];
    __shared__ int spath[NPOLB * AA];
    __shared__ int ssep[BB];
    __shared__ float rs0[TPB / 32], rs1[TPB / 32];

    int pb  = blockIdx.x;
    int p   = pb / BB;
    int b   = pb % BB;
    int tid = threadIdx.x;

    // stage polar structs (8 * 16 words = 128 words)
    if (tid < NPOLB * 16)
        ((float*)sp)[tid] = ((const float*)(g_polar + pb * NPOLB))[tid];
    if (tid < BB)
        ssep[tid] = minsep[((size_t)p * BB + b) * BB + tid];
    __syncthreads();

    int bt = block_type[p * BB + b];
    if (tid < NPOLB * AA) {
        int k  = tid >> 5;
        int aj = tid & 31;
        spath[tid] = pathdist[((size_t)bt * AA + sp[k].a_i) * AA + aj];
    }
    __syncthreads();

    float cutoff    = __ldg(gparams + 0);
    float ramp2     = __ldg(gparams + 1);
    float d2low     = __ldg(gparams + 2);
    float inv_ramp2 = 1.0f / ramp2;
    float d2lr      = d2low + ramp2;

    float s0 = 0.0f, s1 = 0.0f;

    const int slice = NN / SLICES;
    int j0 = blockIdx.y * slice;
    const float4* atomp = g_atom + (size_t)p * NN;
    const float*  volp  = g_vol  + (size_t)p * NN;

    for (int jj = tid; jj < slice; jj += TPB) {
        int j = j0 + jj;
        float4 aj4 = atomp[j];
        float  vol = volp[j];
        int bjj = j >> 5;
        int ajj = j & 31;
        int sep_inter = ssep[bjj];
        bool same = (bjj == b);

        #pragma unroll
        for (int k = 0; k < NPOLB; k++) {
            if (!sp[k].valid) continue;
            float dx = sp[k].xp.x - aj4.x;
            float dy = sp[k].xp.y - aj4.y;
            float dz = sp[k].xp.z - aj4.z;
            float d2 = fmaxf(dx*dx + dy*dy + dz*dz, 0.01f);
            float d  = sqrtf(d2);
            if (d < cutoff && vol > 0.0f) {
                int sep = same ? spath[k * AA + ajj] : sep_inter;
                if (sep >= 4) {
                    float x  = (d - sp[k].w0.w - aj4.w) * sp[k].xp.w;
                    float lk = sp[k].w1.w * vol * __fdividef(__expf(-x * x), d2);
                    // water-occlusion fraction
                    float ax0 = sp[k].w0.x - aj4.x;
                    float ay0 = sp[k].w0.y - aj4.y;
                    float az0 = sp[k].w0.z - aj4.z;
                    float dw0 = ax0*ax0 + ay0*ay0 + az0*az0;
                    float ax1 = sp[k].w1.x - aj4.x;
                    float ay1 = sp[k].w1.y - aj4.y;
                    float az1 = sp[k].w1.z - aj4.z;
                    float dw1 = ax1*ax1 + ay1*ay1 + az1*az1;
                    float m  = fminf(dw0, dw1);
                    float wt = __saturatef((d2lr - m) * inv_ramp2);
                    float frac = wt * wt * (3.0f - 2.0f * wt);
                    s0 += lk;
                    s1 += lk * frac;
                }
            }
        }
    }

    // block reduction
    #pragma unroll
    for (int off = 16; off > 0; off >>= 1) {
        s0 += __shfl_down_sync(0xffffffff, s0, off);
        s1 += __shfl_down_sync(0xffffffff, s1, off);
    }
    int wid = tid >> 5, lane = tid & 31;
    if (lane == 0) { rs0[wid] = s0; rs1[wid] = s1; }
    __syncthreads();
    if (wid == 0) {
        s0 = (lane < TPB / 32) ? rs0[lane] : 0.0f;
        s1 = (lane < TPB / 32) ? rs1[lane] : 0.0f;
        #pragma unroll
        for (int off = 4; off > 0; off >>= 1) {
            s0 += __shfl_down_sync(0xffffffff, s0, off);
            s1 += __shfl_down_sync(0xffffffff, s1, off);
        }
        if (lane == 0) {
            atomicAdd(out + p, s0);
            atomicAdd(out + PP + p, s1);
        }
    }
}

// ---------------------------------------------------------------------------
extern "C" void kernel_launch(void* const* d_in, const int* in_sizes, int n_in,
                              void* d_out, int out_size)
{
    const float* pose_coords = (const float*)d_in[0];
    const int*   block_type  = (const int*)  d_in[1];
    const int*   minsep      = (const int*)  d_in[2];
    // d_in[3] bt_n_atoms unused (all A)
    const int*   bonds       = (const int*)  d_in[4];
    const int*   ranges      = (const int*)  d_in[5];
    const int*   n_donH      = (const int*)  d_in[6];
    const int*   n_acc       = (const int*)  d_in[7];
    const int*   donH_inds   = (const int*)  d_in[8];
    const int*   don_hvy     = (const int*)  d_in[9];
    const int*   acc_inds    = (const int*)  d_in[10];
    const int*   hyb         = (const int*)  d_in[11];
    const int*   is_h        = (const int*)  d_in[12];
    const float* params      = (const float*)d_in[13];
    const int*   pathdist    = (const int*)  d_in[14];
    const float* gparams     = (const float*)d_in[15];
    const float* wgen        = (const float*)d_in[16];
    const float* sp2t        = (const float*)d_in[17];
    const float* sp3t        = (const float*)d_in[18];
    const float* ringt       = (const float*)d_in[19];
    float* out = (float*)d_out;

    int nthreads = PP * NN;  // 6144 covers atoms (6144), polars (1536), out (4)
    lkball_setup_kernel<<<(nthreads + 255) / 256, 256>>>(
        pose_coords, block_type, bonds, ranges, n_donH, n_acc,
        donH_inds, don_hvy, acc_inds, hyb, is_h, params,
        wgen, sp2t, sp3t, ringt, out);

    dim3 grid(PP * BB, SLICES);
    lkball_pair_kernel<<<grid, TPB>>>(gparams, minsep, pathdist, block_type, out);
}

// round 15
// speedup vs baseline: 1.4460x; 1.4460x over previous
#include <cuda_runtime.h>

#define PP 2
#define BB 96
#define AA 32
#define NN (BB*AA)            // 3072 atoms per pose
#define MD 4
#define MA 4
#define NPOLB (MD+MA)         // 8 polars per residue block
#define SLICES 3
#define TPB 256
#define SLICE (NN/SLICES)     // 1024
#define JITER (SLICE/TPB)     // 4
#define NBLK (PP*BB*SLICES)   // 576 blocks
#define C_LK 0.0897935610625833f

__device__ float2 g_partial[NBLK];
__device__ int    g_count = 0;

// ---------------------------------------------------------------------------
// Single fused kernel:
//   - each block: (pose p, residue block b, j-slice)
//   - regenerates the 8 polar/water sites for block b (cheap, redundant x3)
//   - compacts valid polars, stages path/sep rows in SMEM
//   - inner loop over its 1024-atom j slice x nv polars
//   - block partials -> last block does deterministic final reduction
// ---------------------------------------------------------------------------
__global__ __launch_bounds__(TPB, 4)
void lkball_fused_kernel(
    const float* __restrict__ coords,      // (P,N,3)
    const int*   __restrict__ block_type,  // (P,B)
    const int*   __restrict__ minsep,      // (P,B,B)
    const int*   __restrict__ bonds,       // (NT,A,2)
    const int*   __restrict__ ranges,      // (NT,A,2)
    const int*   __restrict__ n_donH,
    const int*   __restrict__ n_acc,
    const int*   __restrict__ donH_inds,   // (NT,MD)
    const int*   __restrict__ don_hvy,     // (NT,MD)
    const int*   __restrict__ acc_inds,    // (NT,MA)
    const int*   __restrict__ hyb,         // (NT,MA)
    const int*   __restrict__ is_h,        // (NT,A)
    const float* __restrict__ params,      // (NT,A,4)
    const int*   __restrict__ pathdist,    // (NT,A,A)
    const float* __restrict__ gparams,     // (3,)
    const float* __restrict__ wgen,        // (2,)
    const float* __restrict__ sp2t,
    const float* __restrict__ sp3t,
    const float* __restrict__ ringt,
    float* __restrict__ out)               // (2,P)
{
    __shared__ float spx[NPOLB], spy[NPOLB], spz[NPOLB];   // polar atom xyz
    __shared__ float sinvl[NPOLB], sri[NPOLB], ssc[NPOLB]; // 1/lam, ri, scale
    __shared__ float sw0x[NPOLB], sw0y[NPOLB], sw0z[NPOLB];
    __shared__ float sw1x[NPOLB], sw1y[NPOLB], sw1z[NPOLB];
    __shared__ int   sai[NPOLB], sval[NPOLB];
    __shared__ int   snv;
    __shared__ int   spath[NPOLB * AA];
    __shared__ int   ssep[BB];
    __shared__ int   sbt[BB];
    __shared__ float rs0[TPB/32], rs1[TPB/32];
    __shared__ int   s_last;

    const int tid = threadIdx.x;
    const int pb  = blockIdx.x;          // p*BB + b
    const int p   = pb / BB;
    const int b   = pb % BB;

    if (tid < BB) {
        sbt[tid]  = block_type[p * BB + tid];
        ssep[tid] = minsep[((size_t)p * BB + b) * BB + tid];
    }
    __syncthreads();

    // ---------------- per-block polar / water generation (threads 0..7) ----
    if (tid < NPOLB) {
        const int k  = tid;
        const int bt = sbt[b];
        const float* cblk = coords + ((size_t)(p * BB + b) * AA) * 3;
        const float wdist = __ldg(wgen + 0);
        const float wang  = __ldg(wgen + 1);

        float w0x_, w0y_, w0z_, w1x_, w1y_, w1z_;
        int a_i, valid;

        if (k < MD) {
            valid = (k < __ldg(n_donH + bt)) ? 1 : 0;
            int hv = __ldg(don_hvy  + bt * MD + k);
            int hi = __ldg(donH_inds + bt * MD + k);
            float hx = cblk[3*hv+0], hy_ = cblk[3*hv+1], hz = cblk[3*hv+2];
            float dx = cblk[3*hi+0]-hx, dy = cblk[3*hi+1]-hy_, dz = cblk[3*hi+2]-hz;
            float inv = rsqrtf(dx*dx + dy*dy + dz*dz + 1e-12f);
            float s = wdist * inv;
            w0x_ = hx + s*dx; w0y_ = hy_ + s*dy; w0z_ = hz + s*dz;
            w1x_ = 1e4f; w1y_ = 1e4f; w1z_ = 1e4f;   // masked water sentinel
            a_i = hv;
        } else {
            int k2 = k - MD;
            valid = (k2 < __ldg(n_acc + bt)) ? 1 : 0;
            int acc = __ldg(acc_inds + bt * MA + k2);
            int r0a   = __ldg(ranges + (bt * AA + acc) * 2 + 0);
            int base  = __ldg(bonds  + (bt * AA + r0a) * 2 + 1);
            int r0b   = __ldg(ranges + (bt * AA + base) * 2 + 0);
            int base2 = __ldg(bonds  + (bt * AA + r0b) * 2 + 1);
            float cx = cblk[3*acc+0],   cy = cblk[3*acc+1],   cz = cblk[3*acc+2];
            float bx = cblk[3*base+0],  by = cblk[3*base+1],  bz = cblk[3*base+2];
            float ax = cblk[3*base2+0], ay = cblk[3*base2+1], az = cblk[3*base2+2];
            float e1x = cx-bx, e1y = cy-by, e1z = cz-bz;
            float inv1 = rsqrtf(e1x*e1x + e1y*e1y + e1z*e1z + 1e-12f);
            e1x *= inv1; e1y *= inv1; e1z *= inv1;
            float ux = bx-ax, uy = by-ay, uz = bz-az;
            float nx = uy*e1z - uz*e1y;
            float ny = uz*e1x - ux*e1z;
            float nz = ux*e1y - uy*e1x;
            float inv2 = rsqrtf(nx*nx + ny*ny + nz*nz + 1e-12f);
            nx *= inv2; ny *= inv2; nz *= inv2;
            float e2x = ny*e1z - nz*e1y;
            float e2y = nz*e1x - nx*e1z;
            float e2z = nx*e1y - ny*e1x;
            int h = __ldg(hyb + bt * MA + k2);
            const float* tors = (h == 0) ? sp2t : ((h == 1) ? sp3t : ringt);
            float chi0 = __ldg(tors + 0), chi1 = __ldg(tors + 1);
            float ct = cosf(wang), st = sinf(wang);
            float f1 = -wdist * ct;
            float fw = wdist * st;
            float c0 = fw * cosf(chi0), s0_ = fw * sinf(chi0);
            float c1 = fw * cosf(chi1), s1_ = fw * sinf(chi1);
            w0x_ = cx + f1*e1x + c0*e2x + s0_*nx;
            w0y_ = cy + f1*e1y + c0*e2y + s0_*ny;
            w0z_ = cz + f1*e1z + c0*e2z + s0_*nz;
            w1x_ = cx + f1*e1x + c1*e2x + s1_*nx;
            w1y_ = cy + f1*e1y + c1*e2y + s1_*ny;
            w1z_ = cz + f1*e1z + c1*e2z + s1_*nz;
            a_i = acc;
        }

        float ri   = __ldg(params + (bt * AA + a_i) * 4 + 0);
        float dgi  = __ldg(params + (bt * AA + a_i) * 4 + 1);
        float lami = __ldg(params + (bt * AA + a_i) * 4 + 2);
        float invl = 1.0f / lami;

        spx[k] = cblk[3*a_i+0]; spy[k] = cblk[3*a_i+1]; spz[k] = cblk[3*a_i+2];
        sinvl[k] = invl; sri[k] = ri; ssc[k] = C_LK * dgi * invl;
        sw0x[k] = w0x_; sw0y[k] = w0y_; sw0z[k] = w0z_;
        sw1x[k] = w1x_; sw1y[k] = w1y_; sw1z[k] = w1z_;
        sai[k] = a_i; sval[k] = valid;
    }
    __syncthreads();

    // ---------------- compact valid polars (deterministic, thread 0) -------
    if (tid == 0) {
        int nv = 0;
        for (int k = 0; k < NPOLB; k++) {
            if (sval[k]) {
                if (nv != k) {
                    spx[nv]=spx[k]; spy[nv]=spy[k]; spz[nv]=spz[k];
                    sinvl[nv]=sinvl[k]; sri[nv]=sri[k]; ssc[nv]=ssc[k];
                    sw0x[nv]=sw0x[k]; sw0y[nv]=sw0y[k]; sw0z[nv]=sw0z[k];
                    sw1x[nv]=sw1x[k]; sw1y[nv]=sw1y[k]; sw1z[nv]=sw1z[k];
                    sai[nv]=sai[k];
                }
                nv++;
            }
        }
        snv = nv;
    }
    __syncthreads();

    const int nv = snv;
    {
        int k = tid >> 5;
        if (tid < nv * AA)
            spath[tid] = __ldg(pathdist + ((size_t)sbt[b] * AA + sai[k]) * AA + (tid & 31));
    }
    __syncthreads();

    const float cutoff    = __ldg(gparams + 0);
    const float ramp2     = __ldg(gparams + 1);
    const float inv_ramp2 = 1.0f / ramp2;
    const float d2lr      = __ldg(gparams + 2) + ramp2;

    float s0 = 0.0f, s1 = 0.0f;

    const int j0 = blockIdx.y * SLICE;
    const float* cp = coords + (size_t)p * NN * 3;

    #pragma unroll
    for (int it = 0; it < JITER; it++) {
        int j  = j0 + it * TPB + tid;
        int bj = j >> 5;
        int aj = j & 31;
        int btj = sbt[bj];
        if (__ldg(is_h + btj * AA + aj)) continue;   // hydrogens never contribute
        float cx = __ldg(cp + 3*j+0), cy = __ldg(cp + 3*j+1), cz = __ldg(cp + 3*j+2);
        float rj  = __ldg(params + (btj * AA + aj) * 4 + 0);
        float vol = __ldg(params + (btj * AA + aj) * 4 + 3);
        int  sep_inter = ssep[bj];
        bool same = (bj == b);

        for (int kk = 0; kk < nv; kk++) {
            float dx = spx[kk] - cx;
            float dy = spy[kk] - cy;
            float dz = spz[kk] - cz;
            float d2 = fmaxf(dx*dx + dy*dy + dz*dz, 0.01f);
            float d  = sqrtf(d2);
            if (d < cutoff) {
                int sep = same ? spath[kk * AA + aj] : sep_inter;
                if (sep >= 4) {
                    float x  = (d - sri[kk] - rj) * sinvl[kk];
                    float lk = ssc[kk] * vol * __fdividef(__expf(-x * x), d2);
                    float ax0 = sw0x[kk]-cx, ay0 = sw0y[kk]-cy, az0 = sw0z[kk]-cz;
                    float dw0 = ax0*ax0 + ay0*ay0 + az0*az0;
                    float ax1 = sw1x[kk]-cx, ay1 = sw1y[kk]-cy, az1 = sw1z[kk]-cz;
                    float dw1 = ax1*ax1 + ay1*ay1 + az1*az1;
                    float m  = fminf(dw0, dw1);
                    float wt = __saturatef((d2lr - m) * inv_ramp2);
                    float frac = wt * wt * (3.0f - 2.0f * wt);
                    s0 += lk;
                    s1 += lk * frac;
                }
            }
        }
    }

    // ---------------- block reduction -> partial -------------------------
    #pragma unroll
    for (int off = 16; off > 0; off >>= 1) {
        s0 += __shfl_down_sync(0xffffffff, s0, off);
        s1 += __shfl_down_sync(0xffffffff, s1, off);
    }
    int wid = tid >> 5, lane = tid & 31;
    if (lane == 0) { rs0[wid] = s0; rs1[wid] = s1; }
    __syncthreads();
    if (tid == 0) {
        float a0 = 0.0f, a1 = 0.0f;
        #pragma unroll
        for (int w = 0; w < TPB/32; w++) { a0 += rs0[w]; a1 += rs1[w]; }
        int flat = blockIdx.y * gridDim.x + blockIdx.x;
        g_partial[flat] = make_float2(a0, a1);
        __threadfence();
        int old = atomicAdd(&g_count, 1);
        s_last = (old == NBLK - 1) ? 1 : 0;
    }
    __syncthreads();

    // ---------------- last block: deterministic final reduction ----------
    if (s_last) {
        __threadfence();
        float a00 = 0.f, a01 = 0.f, a10 = 0.f, a11 = 0.f;  // [pose][term]
        for (int idx = tid; idx < NBLK; idx += TPB) {
            float2 v = g_partial[idx];
            int pp = ((idx % (PP*BB)) / BB);
            if (pp == 0) { a00 += v.x; a01 += v.y; }
            else         { a10 += v.x; a11 += v.y; }
        }
        #pragma unroll
        for (int off = 16; off > 0; off >>= 1) {
            a00 += __shfl_down_sync(0xffffffff, a00, off);
            a01 += __shfl_down_sync(0xffffffff, a01, off);
            a10 += __shfl_down_sync(0xffffffff, a10, off);
            a11 += __shfl_down_sync(0xffffffff, a11, off);
        }
        __shared__ float fin[4][TPB/32];
        if (lane == 0) {
            fin[0][wid] = a00; fin[1][wid] = a01;
            fin[2][wid] = a10; fin[3][wid] = a11;
        }
        __syncthreads();
        if (tid == 0) {
            float o0=0.f,o1=0.f,o2=0.f,o3=0.f;
            #pragma unroll
            for (int w = 0; w < TPB/32; w++) {
                o0 += fin[0][w]; o1 += fin[1][w];
                o2 += fin[2][w]; o3 += fin[3][w];
            }
            out[0]      = o0;   // lk sum, pose 0
            out[1]      = o2;   // lk sum, pose 1
            out[PP + 0] = o1;   // lk*frac, pose 0
            out[PP + 1] = o3;   // lk*frac, pose 1
            g_count = 0;        // reset for next (graph-replayed) launch
        }
    }
}

// ---------------------------------------------------------------------------
extern "C" void kernel_launch(void* const* d_in, const int* in_sizes, int n_in,
                              void* d_out, int out_size)
{
    const float* pose_coords = (const float*)d_in[0];
    const int*   block_type  = (const int*)  d_in[1];
    const int*   minsep      = (const int*)  d_in[2];
    const int*   bonds       = (const int*)  d_in[4];
    const int*   ranges      = (const int*)  d_in[5];
    const int*   n_donH      = (const int*)  d_in[6];
    const int*   n_acc       = (const int*)  d_in[7];
    const int*   donH_inds   = (const int*)  d_in[8];
    const int*   don_hvy     = (const int*)  d_in[9];
    const int*   acc_inds    = (const int*)  d_in[10];
    const int*   hyb         = (const int*)  d_in[11];
    const int*   is_h        = (const int*)  d_in[12];
    const float* params      = (const float*)d_in[13];
    const int*   pathdist    = (const int*)  d_in[14];
    const float* gparams     = (const float*)d_in[15];
    const float* wgen        = (const float*)d_in[16];
    const float* sp2t        = (const float*)d_in[17];
    const float* sp3t        = (const float*)d_in[18];
    const float* ringt       = (const float*)d_in[19];
    float* out = (float*)d_out;

    dim3 grid(PP * BB, SLICES);
    lkball_fused_kernel<<<grid, TPB>>>(
        pose_coords, block_type, minsep, bonds, ranges, n_donH, n_acc,
        donH_inds, don_hvy, acc_inds, hyb, is_h, params, pathdist,
        gparams, wgen, sp2t, sp3t, ringt, out);
}